// round 1
// baseline (speedup 1.0000x reference)
#include <cuda_runtime.h>

#define NN 50000
#define NE 800000
#define ETOT (NE + NN)
#define NH 4
#define HD 64
#define HCC 256
#define NT 200000
#define NEG_SLOPE 0.2f

// ---------------- scratch (static device globals; no allocations) ----------------
__device__ float g_h[(size_t)NN * HCC];     // transformed features [N, H*C]
__device__ float g_feat[(size_t)NN * HD];   // per-layer node output [N, 64]
__device__ float g_ssrc[NN * NH];
__device__ float g_sdst[NN * NH];
__device__ int   g_deg[NN];
__device__ int   g_off[NN + 1];
__device__ int   g_pos[NN];
__device__ int   g_csr[ETOT];
__device__ float g_cs1[HD];
__device__ float g_cs2[HD];

// ---------------- helpers ----------------
__device__ __forceinline__ float warpMax(float v) {
#pragma unroll
    for (int o = 16; o; o >>= 1) v = fmaxf(v, __shfl_xor_sync(0xffffffffu, v, o));
    return v;
}
__device__ __forceinline__ float warpSum(float v) {
#pragma unroll
    for (int o = 16; o; o >>= 1) v += __shfl_xor_sync(0xffffffffu, v, o);
    return v;
}

// ---------------- CSR build ----------------
__global__ void k_zero_deg() {
    int i = blockIdx.x * blockDim.x + threadIdx.x;
    if (i < NN) g_deg[i] = 0;
}

__global__ void k_hist(const int* __restrict__ ei) {
    int i = blockIdx.x * blockDim.x + threadIdx.x;
    if (i >= ETOT) return;
    int dst = (i < NE) ? ei[NE + i] : (i - NE);
    atomicAdd(&g_deg[dst], 1);
}

__global__ void k_scan() {
    __shared__ int sm[1024];
    int t = threadIdx.x;
    const int per = (NN + 1023) / 1024;
    int base = t * per;
    int s = 0;
    for (int j = 0; j < per; j++) {
        int idx = base + j;
        if (idx < NN) s += g_deg[idx];
    }
    sm[t] = s;
    __syncthreads();
    for (int off = 1; off < 1024; off <<= 1) {
        int v = (t >= off) ? sm[t - off] : 0;
        __syncthreads();
        sm[t] += v;
        __syncthreads();
    }
    int run = sm[t] - s;  // exclusive prefix
    for (int j = 0; j < per; j++) {
        int idx = base + j;
        if (idx < NN) {
            g_off[idx] = run;
            g_pos[idx] = run;
            run += g_deg[idx];
        }
    }
    if (t == 0) g_off[NN] = ETOT;
}

__global__ void k_scatter(const int* __restrict__ ei) {
    int i = blockIdx.x * blockDim.x + threadIdx.x;
    if (i >= ETOT) return;
    int src, dst;
    if (i < NE) { src = ei[i]; dst = ei[NE + i]; }
    else        { src = i - NE; dst = src; }
    int p = atomicAdd(&g_pos[dst], 1);
    g_csr[p] = src;
}

// ---------------- GEMM: g_h[M, 256] = A[M, K] @ B[K, 256] ----------------
__global__ void __launch_bounds__(256) k_gemm(const float* __restrict__ A,
                                              const float* __restrict__ B,
                                              int M, int K, int useFeat) {
    __shared__ float As[64][33];
    __shared__ float Bs[32][64];
    const float* Ap = useFeat ? g_feat : A;
    int bx = blockIdx.x & 3;
    int by = blockIdx.x >> 2;
    int tid = threadIdx.x;
    int tx = tid & 15, ty = tid >> 4;
    int row0 = by * 64, col0 = bx * 64;
    float acc[4][4];
#pragma unroll
    for (int i = 0; i < 4; i++)
#pragma unroll
        for (int j = 0; j < 4; j++) acc[i][j] = 0.f;

    for (int k0 = 0; k0 < K; k0 += 32) {
#pragma unroll
        for (int j = 0; j < 8; j++) {
            int l = tid + 256 * j;
            int m = l >> 5, k = l & 31;
            int r = row0 + m;
            As[m][k] = (r < M) ? Ap[(size_t)r * K + k0 + k] : 0.f;
        }
#pragma unroll
        for (int j = 0; j < 8; j++) {
            int l = tid + 256 * j;
            int kb = l >> 6, n = l & 63;
            Bs[kb][n] = B[(size_t)(k0 + kb) * HCC + col0 + n];
        }
        __syncthreads();
#pragma unroll
        for (int kk = 0; kk < 32; kk++) {
            float a0 = As[ty * 4 + 0][kk];
            float a1 = As[ty * 4 + 1][kk];
            float a2 = As[ty * 4 + 2][kk];
            float a3 = As[ty * 4 + 3][kk];
            float4 b = *(const float4*)&Bs[kk][tx * 4];
            acc[0][0] += a0 * b.x; acc[0][1] += a0 * b.y; acc[0][2] += a0 * b.z; acc[0][3] += a0 * b.w;
            acc[1][0] += a1 * b.x; acc[1][1] += a1 * b.y; acc[1][2] += a1 * b.z; acc[1][3] += a1 * b.w;
            acc[2][0] += a2 * b.x; acc[2][1] += a2 * b.y; acc[2][2] += a2 * b.z; acc[2][3] += a2 * b.w;
            acc[3][0] += a3 * b.x; acc[3][1] += a3 * b.y; acc[3][2] += a3 * b.z; acc[3][3] += a3 * b.w;
        }
        __syncthreads();
    }
#pragma unroll
    for (int i = 0; i < 4; i++) {
        int r = row0 + ty * 4 + i;
        if (r < M) {
            float4 o = make_float4(acc[i][0], acc[i][1], acc[i][2], acc[i][3]);
            *(float4*)&g_h[(size_t)r * HCC + col0 + tx * 4] = o;
        }
    }
}

// ---------------- per-node attention scores ----------------
__global__ void k_scores(const float* __restrict__ a_src, const float* __restrict__ a_dst) {
    int idx = blockIdx.x * blockDim.x + threadIdx.x;
    if (idx >= NN * NH) return;
    int n = idx >> 2, h = idx & 3;
    const float* hr  = g_h + (size_t)n * HCC + h * HD;
    const float* asr = a_src + h * HD;
    const float* adr = a_dst + h * HD;
    float s1 = 0.f, s2 = 0.f;
#pragma unroll 8
    for (int c = 0; c < HD; c++) {
        float v = hr[c];
        s1 += v * asr[c];
        s2 += v * adr[c];
    }
    g_ssrc[idx] = s1;
    g_sdst[idx] = s2;
}

// ---------------- GAT aggregate: warp per dst node, gather-based softmax ----------------
__global__ void __launch_bounds__(256) k_aggregate(const float* __restrict__ bias) {
    int w = (blockIdx.x * blockDim.x + threadIdx.x) >> 5;
    int lane = threadIdx.x & 31;
    if (w >= NN) return;
    int beg = g_off[w], end = g_off[w + 1];

    float sd0 = g_sdst[w * 4 + 0];
    float sd1 = g_sdst[w * 4 + 1];
    float sd2 = g_sdst[w * 4 + 2];
    float sd3 = g_sdst[w * 4 + 3];

    // pass 1: per-head max
    float m0 = -1e30f, m1 = -1e30f, m2 = -1e30f, m3 = -1e30f;
    for (int i = beg + lane; i < end; i += 32) {
        int u = g_csr[i];
        const float* ss = g_ssrc + u * 4;
        float e0 = ss[0] + sd0; e0 = e0 > 0.f ? e0 : NEG_SLOPE * e0;
        float e1 = ss[1] + sd1; e1 = e1 > 0.f ? e1 : NEG_SLOPE * e1;
        float e2 = ss[2] + sd2; e2 = e2 > 0.f ? e2 : NEG_SLOPE * e2;
        float e3 = ss[3] + sd3; e3 = e3 > 0.f ? e3 : NEG_SLOPE * e3;
        m0 = fmaxf(m0, e0); m1 = fmaxf(m1, e1); m2 = fmaxf(m2, e2); m3 = fmaxf(m3, e3);
    }
    m0 = warpMax(m0); m1 = warpMax(m1); m2 = warpMax(m2); m3 = warpMax(m3);

    // pass 2: per-head denominator
    float s0 = 0.f, s1 = 0.f, s2 = 0.f, s3 = 0.f;
    for (int i = beg + lane; i < end; i += 32) {
        int u = g_csr[i];
        const float* ss = g_ssrc + u * 4;
        float e0 = ss[0] + sd0; e0 = e0 > 0.f ? e0 : NEG_SLOPE * e0;
        float e1 = ss[1] + sd1; e1 = e1 > 0.f ? e1 : NEG_SLOPE * e1;
        float e2 = ss[2] + sd2; e2 = e2 > 0.f ? e2 : NEG_SLOPE * e2;
        float e3 = ss[3] + sd3; e3 = e3 > 0.f ? e3 : NEG_SLOPE * e3;
        s0 += __expf(e0 - m0); s1 += __expf(e1 - m1);
        s2 += __expf(e2 - m2); s3 += __expf(e3 - m3);
    }
    s0 = warpSum(s0); s1 = warpSum(s1); s2 = warpSum(s2); s3 = warpSum(s3);
    float inv0 = 1.f / (s0 + 1e-16f);
    float inv1 = 1.f / (s1 + 1e-16f);
    float inv2 = 1.f / (s2 + 1e-16f);
    float inv3 = 1.f / (s3 + 1e-16f);

    // pass 3: weighted accumulate of h[src]; lanes own channels (lane + 32k)
    float acc[8];
#pragma unroll
    for (int k = 0; k < 8; k++) acc[k] = 0.f;

    for (int i = beg; i < end; ++i) {
        int u = g_csr[i];
        float wv = 0.f;
        if (lane < 4) {
            float sv  = g_ssrc[u * 4 + lane];
            float sdl = lane == 0 ? sd0 : lane == 1 ? sd1 : lane == 2 ? sd2 : sd3;
            float mv  = lane == 0 ? m0  : lane == 1 ? m1  : lane == 2 ? m2  : m3;
            float iv  = lane == 0 ? inv0 : lane == 1 ? inv1 : lane == 2 ? inv2 : inv3;
            float e = sv + sdl; e = e > 0.f ? e : NEG_SLOPE * e;
            wv = __expf(e - mv) * iv;
        }
        float w0 = __shfl_sync(0xffffffffu, wv, 0);
        float w1 = __shfl_sync(0xffffffffu, wv, 1);
        float w2 = __shfl_sync(0xffffffffu, wv, 2);
        float w3 = __shfl_sync(0xffffffffu, wv, 3);
        const float* hr = g_h + (size_t)u * HCC;
#pragma unroll
        for (int k = 0; k < 8; k++) {
            float wk = (k < 2) ? w0 : (k < 4) ? w1 : (k < 6) ? w2 : w3;  // head = k>>1
            acc[k] += wk * hr[lane + 32 * k];
        }
    }

    // mean over heads + bias
    float o0 = (acc[0] + acc[2] + acc[4] + acc[6]) * 0.25f + bias[lane];
    float o1 = (acc[1] + acc[3] + acc[5] + acc[7]) * 0.25f + bias[lane + 32];
    g_feat[(size_t)w * HD + lane]      = o0;
    g_feat[(size_t)w * HD + lane + 32] = o1;
}

// ---------------- GraphNorm ----------------
__global__ void k_zero_stats() {
    int t = threadIdx.x;
    if (t < HD) { g_cs1[t] = 0.f; g_cs2[t] = 0.f; }
}

__global__ void k_colreduce(int mode, const float* __restrict__ gs) {
    int t = threadIdx.x;
    int c = t & 63;
    int g = t >> 6;  // 4 row-groups
    float mu = 0.f, sc = 0.f;
    if (mode) { mu = g_cs1[c] * (1.f / NN); sc = gs[c]; }
    float acc = 0.f;
    for (int r = blockIdx.x * 4 + g; r < NN; r += gridDim.x * 4) {
        float v = g_feat[(size_t)r * HD + c];
        if (mode) { float xc = v - mu * sc; acc += xc * xc; }
        else acc += v;
    }
    __shared__ float sm[256];
    sm[t] = acc;
    __syncthreads();
    if (t < 64) {
        float s = sm[t] + sm[t + 64] + sm[t + 128] + sm[t + 192];
        atomicAdd(mode ? &g_cs2[c] : &g_cs1[c], s);
    }
}

__global__ void k_norm_relu(const float* __restrict__ w, const float* __restrict__ b,
                            const float* __restrict__ gs) {
    int idx = blockIdx.x * blockDim.x + threadIdx.x;
    if (idx >= NN * HD) return;
    int c = idx & 63;
    float mu  = g_cs1[c] * (1.f / NN);
    float var = g_cs2[c] * (1.f / NN);
    float r = rsqrtf(var + 1e-5f);
    float xc = g_feat[idx] - mu * gs[c];
    float o = w[c] * xc * r + b[c];
    g_feat[idx] = o > 0.f ? o : 0.f;
}

// ---------------- triplet gather + layernorm + fc ----------------
__global__ void __launch_bounds__(256) k_triplet(const int* __restrict__ trip,
        const float* __restrict__ lnw, const float* __restrict__ lnb,
        const float* __restrict__ fcw, const float* __restrict__ fcb,
        float* __restrict__ out) {
    int w = (blockIdx.x * blockDim.x + threadIdx.x) >> 5;
    int lane = threadIdx.x & 31;
    if (w >= NT) return;
    int n0 = trip[w * 4 + 0];
    int n1 = trip[w * 4 + 1];
    int n2 = trip[w * 4 + 2];
    int n3 = trip[w * 4 + 3];
    float v[8];
#pragma unroll
    for (int k = 0; k < 8; k++) {
        int i = lane + 32 * k;
        int node = (k < 2) ? n0 : (k < 4) ? n1 : (k < 6) ? n2 : n3;  // i>>6 == k>>1
        v[k] = g_feat[(size_t)node * HD + (i & 63)];
    }
    float s = 0.f;
#pragma unroll
    for (int k = 0; k < 8; k++) s += v[k];
    s = warpSum(s);
    float mean = s * (1.f / 256.f);
    float q = 0.f;
#pragma unroll
    for (int k = 0; k < 8; k++) { float d = v[k] - mean; q += d * d; }
    q = warpSum(q);
    float r = rsqrtf(q * (1.f / 256.f) + 1e-5f);
    float acc = 0.f;
#pragma unroll
    for (int k = 0; k < 8; k++) {
        int i = lane + 32 * k;
        acc += ((v[k] - mean) * r * lnw[i] + lnb[i]) * fcw[i];
    }
    acc = warpSum(acc);
    if (lane == 0) out[w] = acc + fcb[0];
}

// ---------------- launch ----------------
extern "C" void kernel_launch(void* const* d_in, const int* in_sizes, int n_in,
                              void* d_out, int out_size) {
    const float* x   = (const float*)d_in[0];
    const float* W1  = (const float*)d_in[2];
    const float* as1 = (const float*)d_in[3];
    const float* ad1 = (const float*)d_in[4];
    const float* b1  = (const float*)d_in[5];
    const float* W2  = (const float*)d_in[6];
    const float* as2 = (const float*)d_in[7];
    const float* ad2 = (const float*)d_in[8];
    const float* b2  = (const float*)d_in[9];
    const float* g1w = (const float*)d_in[10];
    const float* g1b = (const float*)d_in[11];
    const float* g1s = (const float*)d_in[12];
    const float* g2w = (const float*)d_in[13];
    const float* g2b = (const float*)d_in[14];
    const float* g2s = (const float*)d_in[15];
    const float* lnw = (const float*)d_in[16];
    const float* lnb = (const float*)d_in[17];
    const float* fcw = (const float*)d_in[18];
    const float* fcb = (const float*)d_in[19];
    const int*   ei  = (const int*)d_in[20];
    const int*   trp = (const int*)d_in[21];
    float* out = (float*)d_out;

    // CSR build (dst-sorted adjacency incl. self loops)
    k_zero_deg<<<(NN + 255) / 256, 256>>>();
    k_hist<<<(ETOT + 255) / 256, 256>>>(ei);
    k_scan<<<1, 1024>>>();
    k_scatter<<<(ETOT + 255) / 256, 256>>>(ei);

    int gemmGrid = ((NN + 63) / 64) * 4;

    // ---- layer 1 ----
    k_gemm<<<gemmGrid, 256>>>(x, W1, NN, 128, 0);
    k_scores<<<(NN * NH + 255) / 256, 256>>>(as1, ad1);
    k_aggregate<<<(NN + 7) / 8, 256>>>(b1);
    k_zero_stats<<<1, 128>>>();
    k_colreduce<<<128, 256>>>(0, g1s);
    k_colreduce<<<128, 256>>>(1, g1s);
    k_norm_relu<<<(NN * HD + 255) / 256, 256>>>(g1w, g1b, g1s);

    // ---- layer 2 ----
    k_gemm<<<gemmGrid, 256>>>(nullptr, W2, NN, 64, 1);
    k_scores<<<(NN * NH + 255) / 256, 256>>>(as2, ad2);
    k_aggregate<<<(NN + 7) / 8, 256>>>(b2);
    k_zero_stats<<<1, 128>>>();
    k_colreduce<<<128, 256>>>(0, g2s);
    k_colreduce<<<128, 256>>>(1, g2s);
    k_norm_relu<<<(NN * HD + 255) / 256, 256>>>(g2w, g2b, g2s);

    // ---- triplet head ----
    k_triplet<<<(NT + 7) / 8, 256>>>(trp, lnw, lnb, fcw, fcb, out);
}

// round 2
// speedup vs baseline: 1.7057x; 1.7057x over previous
#include <cuda_runtime.h>

#define NN 50000
#define NE 800000
#define ETOT (NE + NN)
#define NH 4
#define HD 64
#define HCC 256
#define NT 200000
#define NEG_SLOPE 0.2f

// ---------------- scratch (static device globals; no allocations) ----------------
__device__ float g_h[(size_t)NN * HCC];     // transformed features [N, H*C]
__device__ float g_feat[(size_t)NN * HD];   // per-layer node output [N, 64]
__device__ float g_ssrc[NN * NH];
__device__ float g_sdst[NN * NH];
__device__ int   g_deg[NN];
__device__ int   g_off[NN + 1];
__device__ int   g_pos[NN];
__device__ int   g_csr[ETOT];
__device__ float g_cs1[HD];
__device__ float g_cs2[HD];

// ---------------- helpers ----------------
__device__ __forceinline__ float warpMax(float v) {
#pragma unroll
    for (int o = 16; o; o >>= 1) v = fmaxf(v, __shfl_xor_sync(0xffffffffu, v, o));
    return v;
}
__device__ __forceinline__ float warpSum(float v) {
#pragma unroll
    for (int o = 16; o; o >>= 1) v += __shfl_xor_sync(0xffffffffu, v, o);
    return v;
}
__device__ __forceinline__ unsigned f2tf(float f) {
    unsigned r;
    asm("cvt.rna.tf32.f32 %0, %1;" : "=r"(r) : "f"(f));
    return r;
}
__device__ __forceinline__ void mma_tf32(float* d, const unsigned* a, const unsigned* b) {
    asm volatile(
        "mma.sync.aligned.m16n8k8.row.col.f32.tf32.tf32.f32 "
        "{%0,%1,%2,%3}, {%4,%5,%6,%7}, {%8,%9}, {%0,%1,%2,%3};"
        : "+f"(d[0]), "+f"(d[1]), "+f"(d[2]), "+f"(d[3])
        : "r"(a[0]), "r"(a[1]), "r"(a[2]), "r"(a[3]), "r"(b[0]), "r"(b[1]));
}

// ---------------- CSR build ----------------
__global__ void k_zero_deg() {
    int i = blockIdx.x * blockDim.x + threadIdx.x;
    if (i < NN) g_deg[i] = 0;
}

__global__ void k_hist(const int* __restrict__ ei) {
    int i = blockIdx.x * blockDim.x + threadIdx.x;
    if (i >= ETOT) return;
    int dst = (i < NE) ? ei[NE + i] : (i - NE);
    atomicAdd(&g_deg[dst], 1);
}

__global__ void k_scan() {
    __shared__ int sm[1024];
    int t = threadIdx.x;
    const int per = (NN + 1023) / 1024;
    int base = t * per;
    int s = 0;
    for (int j = 0; j < per; j++) {
        int idx = base + j;
        if (idx < NN) s += g_deg[idx];
    }
    sm[t] = s;
    __syncthreads();
    for (int off = 1; off < 1024; off <<= 1) {
        int v = (t >= off) ? sm[t - off] : 0;
        __syncthreads();
        sm[t] += v;
        __syncthreads();
    }
    int run = sm[t] - s;  // exclusive prefix
    for (int j = 0; j < per; j++) {
        int idx = base + j;
        if (idx < NN) {
            g_off[idx] = run;
            g_pos[idx] = run;
            run += g_deg[idx];
        }
    }
    if (t == 0) g_off[NN] = ETOT;
}

__global__ void k_scatter(const int* __restrict__ ei) {
    int i = blockIdx.x * blockDim.x + threadIdx.x;
    if (i >= ETOT) return;
    int src, dst;
    if (i < NE) { src = ei[i]; dst = ei[NE + i]; }
    else        { src = i - NE; dst = src; }
    int p = atomicAdd(&g_pos[dst], 1);
    g_csr[p] = src;
}

// ---------------- tf32 tensor-core GEMM: g_h[M,256] = A[M,K] @ B[K,256] ----------------
// Block tile 128x128, 8 warps (2x4), warp tile 64x32, mma m16n8k8, double-buffered smem.
__global__ void __launch_bounds__(256) k_gemm_tf32(const float* __restrict__ A,
                                                   const float* __restrict__ B,
                                                   int M, int K, int useFeat) {
    __shared__ unsigned As[2][16][136];
    __shared__ unsigned Bs[2][16][136];
    const float* Ap = useFeat ? g_feat : A;

    int tid = threadIdx.x;
    int lane = tid & 31;
    int wid = tid >> 5;
    int warp_m = wid >> 2;   // 0..1
    int warp_n = wid & 3;    // 0..3
    int gid = lane >> 2;     // 0..7
    int tig = lane & 3;      // 0..3

    int colBlk = blockIdx.x & 1;
    int rowBlk = blockIdx.x >> 1;
    int row0 = rowBlk * 128;
    int col0 = colBlk * 128;

    int NC = K / 16;
    float acc[4][4][4];
#pragma unroll
    for (int mt = 0; mt < 4; mt++)
#pragma unroll
        for (int nt = 0; nt < 4; nt++)
#pragma unroll
            for (int q = 0; q < 4; q++) acc[mt][nt][q] = 0.f;

    // A load coords: row = row0 + (tid>>2) + it*64 ; k = (tid&3)*4
    int aRow = tid >> 2;
    int aK4 = (tid & 3) * 4;
    // B load coords: k = (tid>>5) + it*8 ; n = lane*4
    int bK = tid >> 5;
    int bN = lane * 4;

    float4 aReg[2], bReg[2];

    // prologue: load chunk 0
    {
        int k0 = 0;
#pragma unroll
        for (int it = 0; it < 2; it++) {
            int r = row0 + aRow + it * 64;
            aReg[it] = (r < M) ? *(const float4*)(Ap + (size_t)r * K + k0 + aK4)
                               : make_float4(0.f, 0.f, 0.f, 0.f);
            bReg[it] = *(const float4*)(B + (size_t)(k0 + bK + it * 8) * HCC + col0 + bN);
        }
#pragma unroll
        for (int it = 0; it < 2; it++) {
            int rr = aRow + it * 64;
            As[0][aK4 + 0][rr] = f2tf(aReg[it].x);
            As[0][aK4 + 1][rr] = f2tf(aReg[it].y);
            As[0][aK4 + 2][rr] = f2tf(aReg[it].z);
            As[0][aK4 + 3][rr] = f2tf(aReg[it].w);
            unsigned* bp = &Bs[0][bK + it * 8][bN];
            bp[0] = f2tf(bReg[it].x);
            bp[1] = f2tf(bReg[it].y);
            bp[2] = f2tf(bReg[it].z);
            bp[3] = f2tf(bReg[it].w);
        }
    }
    __syncthreads();

    for (int c = 0; c < NC; c++) {
        int buf = c & 1;
        if (c + 1 < NC) {
            int k0 = (c + 1) * 16;
#pragma unroll
            for (int it = 0; it < 2; it++) {
                int r = row0 + aRow + it * 64;
                aReg[it] = (r < M) ? *(const float4*)(Ap + (size_t)r * K + k0 + aK4)
                                   : make_float4(0.f, 0.f, 0.f, 0.f);
                bReg[it] = *(const float4*)(B + (size_t)(k0 + bK + it * 8) * HCC + col0 + bN);
            }
        }
        // compute from buf
        int mrow = warp_m * 64;
        int ncol = warp_n * 32;
#pragma unroll
        for (int ks = 0; ks < 2; ks++) {
            unsigned af[4][4], bf[4][2];
#pragma unroll
            for (int mt = 0; mt < 4; mt++) {
                int rb = mrow + mt * 16 + gid;
                af[mt][0] = As[buf][ks * 8 + tig][rb];
                af[mt][1] = As[buf][ks * 8 + tig][rb + 8];
                af[mt][2] = As[buf][ks * 8 + tig + 4][rb];
                af[mt][3] = As[buf][ks * 8 + tig + 4][rb + 8];
            }
#pragma unroll
            for (int nt = 0; nt < 4; nt++) {
                int nb = ncol + nt * 8 + gid;
                bf[nt][0] = Bs[buf][ks * 8 + tig][nb];
                bf[nt][1] = Bs[buf][ks * 8 + tig + 4][nb];
            }
#pragma unroll
            for (int mt = 0; mt < 4; mt++)
#pragma unroll
                for (int nt = 0; nt < 4; nt++)
                    mma_tf32(acc[mt][nt], af[mt], bf[nt]);
        }
        __syncthreads();
        if (c + 1 < NC) {
            int nb = (c + 1) & 1;
#pragma unroll
            for (int it = 0; it < 2; it++) {
                int rr = aRow + it * 64;
                As[nb][aK4 + 0][rr] = f2tf(aReg[it].x);
                As[nb][aK4 + 1][rr] = f2tf(aReg[it].y);
                As[nb][aK4 + 2][rr] = f2tf(aReg[it].z);
                As[nb][aK4 + 3][rr] = f2tf(aReg[it].w);
                unsigned* bp = &Bs[nb][bK + it * 8][bN];
                bp[0] = f2tf(bReg[it].x);
                bp[1] = f2tf(bReg[it].y);
                bp[2] = f2tf(bReg[it].z);
                bp[3] = f2tf(bReg[it].w);
            }
            __syncthreads();
        }
    }

    // epilogue
#pragma unroll
    for (int mt = 0; mt < 4; mt++) {
        int r = row0 + warp_m * 64 + mt * 16 + gid;
#pragma unroll
        for (int nt = 0; nt < 4; nt++) {
            int cc = col0 + warp_n * 32 + nt * 8 + tig * 2;
            if (r < M)
                *(float2*)(g_h + (size_t)r * HCC + cc) = make_float2(acc[mt][nt][0], acc[mt][nt][1]);
            if (r + 8 < M)
                *(float2*)(g_h + (size_t)(r + 8) * HCC + cc) = make_float2(acc[mt][nt][2], acc[mt][nt][3]);
        }
    }
}

// ---------------- per-node attention scores: warp per node, float4 ----------------
__global__ void __launch_bounds__(256) k_scores(const float* __restrict__ a_src,
                                                const float* __restrict__ a_dst) {
    int w = (blockIdx.x * blockDim.x + threadIdx.x) >> 5;
    int lane = threadIdx.x & 31;
    if (w >= NN) return;
    const float4* hp = (const float4*)(g_h + (size_t)w * HCC + lane * 8);
    float4 h0 = __ldg(hp), h1 = __ldg(hp + 1);
    int head = lane >> 3;
    int cb = (lane & 7) * 8;
    const float4* as = (const float4*)(a_src + head * HD + cb);
    const float4* ad = (const float4*)(a_dst + head * HD + cb);
    float4 a0 = __ldg(as), a1 = __ldg(as + 1);
    float4 d0 = __ldg(ad), d1 = __ldg(ad + 1);
    float p1 = h0.x * a0.x + h0.y * a0.y + h0.z * a0.z + h0.w * a0.w
             + h1.x * a1.x + h1.y * a1.y + h1.z * a1.z + h1.w * a1.w;
    float p2 = h0.x * d0.x + h0.y * d0.y + h0.z * d0.z + h0.w * d0.w
             + h1.x * d1.x + h1.y * d1.y + h1.z * d1.z + h1.w * d1.w;
#pragma unroll
    for (int o = 1; o < 8; o <<= 1) {
        p1 += __shfl_xor_sync(0xffffffffu, p1, o);
        p2 += __shfl_xor_sync(0xffffffffu, p2, o);
    }
    if ((lane & 7) == 0) {
        g_ssrc[w * 4 + head] = p1;
        g_sdst[w * 4 + head] = p2;
    }
}

// ---------------- GAT aggregate: warp per dst, 2-pass softmax, unnormalized accumulate ----------------
__global__ void __launch_bounds__(256) k_aggregate(const float* __restrict__ bias) {
    int w = (blockIdx.x * blockDim.x + threadIdx.x) >> 5;
    int lane = threadIdx.x & 31;
    if (w >= NN) return;
    int beg = g_off[w], end = g_off[w + 1];
    int head = lane >> 3;

    float4 sd = __ldg((const float4*)(g_sdst + w * 4));

    // pass 1: per-head max
    float m0 = -1e30f, m1 = -1e30f, m2 = -1e30f, m3 = -1e30f;
    for (int i = beg + lane; i < end; i += 32) {
        int u = __ldg(&g_csr[i]);
        float4 ss = __ldg((const float4*)(g_ssrc + u * 4));
        float e0 = ss.x + sd.x; e0 = fmaxf(e0, NEG_SLOPE * e0);
        float e1 = ss.y + sd.y; e1 = fmaxf(e1, NEG_SLOPE * e1);
        float e2 = ss.z + sd.z; e2 = fmaxf(e2, NEG_SLOPE * e2);
        float e3 = ss.w + sd.w; e3 = fmaxf(e3, NEG_SLOPE * e3);
        m0 = fmaxf(m0, e0); m1 = fmaxf(m1, e1);
        m2 = fmaxf(m2, e2); m3 = fmaxf(m3, e3);
    }
    m0 = warpMax(m0); m1 = warpMax(m1); m2 = warpMax(m2); m3 = warpMax(m3);

    // lane h (h<4) owns head h's weight computation
    float sdh = lane == 0 ? sd.x : lane == 1 ? sd.y : lane == 2 ? sd.z : sd.w;
    float mhh = lane == 0 ? m0 : lane == 1 ? m1 : lane == 2 ? m2 : m3;

    // pass 2: unnormalized exp-weighted accumulation + denominator
    float4 accA = make_float4(0.f, 0.f, 0.f, 0.f);
    float4 accB = make_float4(0.f, 0.f, 0.f, 0.f);
    float s_loc = 0.f;
    for (int i = beg; i < end; ++i) {
        int u = __ldg(&g_csr[i]);
        float wv = 0.f;
        if (lane < 4) {
            float sv = __ldg(&g_ssrc[u * 4 + lane]);
            float e = sv + sdh;
            e = fmaxf(e, NEG_SLOPE * e);
            wv = __expf(e - mhh);
            s_loc += wv;
        }
        float wk = __shfl_sync(0xffffffffu, wv, head);
        const float4* hp = (const float4*)(g_h + (size_t)u * HCC + lane * 8);
        float4 h0 = __ldg(hp), h1 = __ldg(hp + 1);
        accA.x += wk * h0.x; accA.y += wk * h0.y; accA.z += wk * h0.z; accA.w += wk * h0.w;
        accB.x += wk * h1.x; accB.y += wk * h1.y; accB.z += wk * h1.z; accB.w += wk * h1.w;
    }
    float invl = (lane < 4) ? 1.0f / (s_loc + 1e-16f) : 0.f;
    float inv = __shfl_sync(0xffffffffu, invl, head);
    accA.x *= inv; accA.y *= inv; accA.z *= inv; accA.w *= inv;
    accB.x *= inv; accB.y *= inv; accB.z *= inv; accB.w *= inv;

    // sum over the 4 heads (lanes l, l^8, l^16, l^24 hold the same within-head channels)
#pragma unroll
    for (int o = 8; o < 32; o <<= 1) {
        accA.x += __shfl_xor_sync(0xffffffffu, accA.x, o);
        accA.y += __shfl_xor_sync(0xffffffffu, accA.y, o);
        accA.z += __shfl_xor_sync(0xffffffffu, accA.z, o);
        accA.w += __shfl_xor_sync(0xffffffffu, accA.w, o);
        accB.x += __shfl_xor_sync(0xffffffffu, accB.x, o);
        accB.y += __shfl_xor_sync(0xffffffffu, accB.y, o);
        accB.z += __shfl_xor_sync(0xffffffffu, accB.z, o);
        accB.w += __shfl_xor_sync(0xffffffffu, accB.w, o);
    }
    if (lane < 8) {
        const float4* bp = (const float4*)(bias + lane * 8);
        float4 b0 = __ldg(bp), b1 = __ldg(bp + 1);
        float4 o0 = make_float4(accA.x * 0.25f + b0.x, accA.y * 0.25f + b0.y,
                                accA.z * 0.25f + b0.z, accA.w * 0.25f + b0.w);
        float4 o1 = make_float4(accB.x * 0.25f + b1.x, accB.y * 0.25f + b1.y,
                                accB.z * 0.25f + b1.z, accB.w * 0.25f + b1.w);
        float4* op = (float4*)(g_feat + (size_t)w * HD + lane * 8);
        op[0] = o0;
        op[1] = o1;
    }
}

// ---------------- GraphNorm (single-pass stats via E[x^2]) ----------------
__global__ void k_zero_stats() {
    int t = threadIdx.x;
    if (t < HD) { g_cs1[t] = 0.f; g_cs2[t] = 0.f; }
}

__global__ void k_colreduce() {
    int t = threadIdx.x;
    int c = t & 63;
    int g = t >> 6;  // 4 row-groups
    float a1 = 0.f, a2 = 0.f;
    for (int r = blockIdx.x * 4 + g; r < NN; r += gridDim.x * 4) {
        float v = g_feat[(size_t)r * HD + c];
        a1 += v;
        a2 += v * v;
    }
    __shared__ float s1[256], s2[256];
    s1[t] = a1; s2[t] = a2;
    __syncthreads();
    if (t < 64) {
        float r1 = s1[t] + s1[t + 64] + s1[t + 128] + s1[t + 192];
        float r2 = s2[t] + s2[t + 64] + s2[t + 128] + s2[t + 192];
        atomicAdd(&g_cs1[c], r1);
        atomicAdd(&g_cs2[c], r2);
    }
}

__global__ void k_norm_relu(const float* __restrict__ w, const float* __restrict__ b,
                            const float* __restrict__ gs) {
    int idx = blockIdx.x * blockDim.x + threadIdx.x;
    if (idx >= NN * HD) return;
    int c = idx & 63;
    float mu = g_cs1[c] * (1.f / NN);
    float m2 = g_cs2[c] * (1.f / NN);
    float tt = mu * gs[c];
    float var = m2 - 2.f * tt * mu + tt * tt;
    float r = rsqrtf(var + 1e-5f);
    float xc = g_feat[idx] - tt;
    float o = w[c] * xc * r + b[c];
    g_feat[idx] = o > 0.f ? o : 0.f;
}

// ---------------- triplet gather + layernorm + fc ----------------
__global__ void __launch_bounds__(256) k_triplet(const int* __restrict__ trip,
        const float* __restrict__ lnw, const float* __restrict__ lnb,
        const float* __restrict__ fcw, const float* __restrict__ fcb,
        float* __restrict__ out) {
    int w = (blockIdx.x * blockDim.x + threadIdx.x) >> 5;
    int lane = threadIdx.x & 31;
    if (w >= NT) return;
    int n0 = trip[w * 4 + 0];
    int n1 = trip[w * 4 + 1];
    int n2 = trip[w * 4 + 2];
    int n3 = trip[w * 4 + 3];
    float v[8];
#pragma unroll
    for (int k = 0; k < 8; k++) {
        int i = lane + 32 * k;
        int node = (k < 2) ? n0 : (k < 4) ? n1 : (k < 6) ? n2 : n3;
        v[k] = __ldg(&g_feat[(size_t)node * HD + (i & 63)]);
    }
    float s = 0.f;
#pragma unroll
    for (int k = 0; k < 8; k++) s += v[k];
    s = warpSum(s);
    float mean = s * (1.f / 256.f);
    float q = 0.f;
#pragma unroll
    for (int k = 0; k < 8; k++) { float d = v[k] - mean; q += d * d; }
    q = warpSum(q);
    float r = rsqrtf(q * (1.f / 256.f) + 1e-5f);
    float acc = 0.f;
#pragma unroll
    for (int k = 0; k < 8; k++) {
        int i = lane + 32 * k;
        acc += ((v[k] - mean) * r * lnw[i] + lnb[i]) * fcw[i];
    }
    acc = warpSum(acc);
    if (lane == 0) out[w] = acc + fcb[0];
}

// ---------------- launch ----------------
extern "C" void kernel_launch(void* const* d_in, const int* in_sizes, int n_in,
                              void* d_out, int out_size) {
    const float* x   = (const float*)d_in[0];
    const float* W1  = (const float*)d_in[2];
    const float* as1 = (const float*)d_in[3];
    const float* ad1 = (const float*)d_in[4];
    const float* b1  = (const float*)d_in[5];
    const float* W2  = (const float*)d_in[6];
    const float* as2 = (const float*)d_in[7];
    const float* ad2 = (const float*)d_in[8];
    const float* b2  = (const float*)d_in[9];
    const float* g1w = (const float*)d_in[10];
    const float* g1b = (const float*)d_in[11];
    const float* g1s = (const float*)d_in[12];
    const float* g2w = (const float*)d_in[13];
    const float* g2b = (const float*)d_in[14];
    const float* g2s = (const float*)d_in[15];
    const float* lnw = (const float*)d_in[16];
    const float* lnb = (const float*)d_in[17];
    const float* fcw = (const float*)d_in[18];
    const float* fcb = (const float*)d_in[19];
    const int*   ei  = (const int*)d_in[20];
    const int*   trp = (const int*)d_in[21];
    float* out = (float*)d_out;

    // CSR build (dst-sorted adjacency incl. self loops)
    k_zero_deg<<<(NN + 255) / 256, 256>>>();
    k_hist<<<(ETOT + 255) / 256, 256>>>(ei);
    k_scan<<<1, 1024>>>();
    k_scatter<<<(ETOT + 255) / 256, 256>>>(ei);

    int gemmGrid = ((NN + 127) / 128) * 2;
    int warpGrid = (NN + 7) / 8;

    // ---- layer 1 ----
    k_gemm_tf32<<<gemmGrid, 256>>>(x, W1, NN, 128, 0);
    k_scores<<<warpGrid, 256>>>(as1, ad1);
    k_aggregate<<<warpGrid, 256>>>(b1);
    k_zero_stats<<<1, 128>>>();
    k_colreduce<<<128, 256>>>();
    k_norm_relu<<<(NN * HD + 255) / 256, 256>>>(g1w, g1b, g1s);

    // ---- layer 2 ----
    k_gemm_tf32<<<gemmGrid, 256>>>(nullptr, W2, NN, 64, 1);
    k_scores<<<warpGrid, 256>>>(as2, ad2);
    k_aggregate<<<warpGrid, 256>>>(b2);
    k_zero_stats<<<1, 128>>>();
    k_colreduce<<<128, 256>>>();
    k_norm_relu<<<(NN * HD + 255) / 256, 256>>>(g2w, g2b, g2s);

    // ---- triplet head ----
    k_triplet<<<(NT + 7) / 8, 256>>>(trp, lnw, lnb, fcw, fcb, out);
}

// round 3
// speedup vs baseline: 1.7585x; 1.0310x over previous
#include <cuda_runtime.h>

#define NN 50000
#define NE 800000
#define ETOT (NE + NN)
#define NH 4
#define HD 64
#define HCC 256
#define NT 200000
#define NEG_SLOPE 0.2f

// ---------------- scratch (static device globals; no allocations) ----------------
__device__ float g_h[(size_t)NN * HCC];     // transformed features [N, H*C]
__device__ float g_feat[(size_t)NN * HD];   // per-layer node output [N, 64]
__device__ float g_ssrc[NN * NH];
__device__ float g_sdst[NN * NH];
__device__ int   g_deg[NN];
__device__ int   g_off[NN + 1];
__device__ int   g_pos[NN];
__device__ int   g_csr[ETOT];
__device__ float g_cs1[HD];
__device__ float g_cs2[HD];

// ---------------- helpers ----------------
__device__ __forceinline__ float warpSum(float v) {
#pragma unroll
    for (int o = 16; o; o >>= 1) v += __shfl_xor_sync(0xffffffffu, v, o);
    return v;
}
__device__ __forceinline__ unsigned f2tf(float f) {
    unsigned r;
    asm("cvt.rna.tf32.f32 %0, %1;" : "=r"(r) : "f"(f));
    return r;
}
__device__ __forceinline__ void mma_tf32(float* d, const unsigned* a, const unsigned* b) {
    asm volatile(
        "mma.sync.aligned.m16n8k8.row.col.f32.tf32.tf32.f32 "
        "{%0,%1,%2,%3}, {%4,%5,%6,%7}, {%8,%9}, {%0,%1,%2,%3};"
        : "+f"(d[0]), "+f"(d[1]), "+f"(d[2]), "+f"(d[3])
        : "r"(a[0]), "r"(a[1]), "r"(a[2]), "r"(a[3]), "r"(b[0]), "r"(b[1]));
}

// ---------------- CSR build ----------------
__global__ void k_zero_deg() {
    int i = blockIdx.x * blockDim.x + threadIdx.x;
    if (i < NN) g_deg[i] = 0;
}

__global__ void k_hist(const int* __restrict__ ei) {
    int i = blockIdx.x * blockDim.x + threadIdx.x;
    if (i >= ETOT) return;
    int dst = (i < NE) ? __ldg(&ei[NE + i]) : (i - NE);
    atomicAdd(&g_deg[dst], 1);
}

__global__ void k_scan() {
    __shared__ int sm[1024];
    int t = threadIdx.x;
    const int per = (NN + 1023) / 1024;
    int base = t * per;
    int s = 0;
    for (int j = 0; j < per; j++) {
        int idx = base + j;
        if (idx < NN) s += g_deg[idx];
    }
    sm[t] = s;
    __syncthreads();
    for (int off = 1; off < 1024; off <<= 1) {
        int v = (t >= off) ? sm[t - off] : 0;
        __syncthreads();
        sm[t] += v;
        __syncthreads();
    }
    int run = sm[t] - s;  // exclusive prefix
    for (int j = 0; j < per; j++) {
        int idx = base + j;
        if (idx < NN) {
            g_off[idx] = run;
            g_pos[idx] = run;
            run += g_deg[idx];
        }
    }
    if (t == 0) g_off[NN] = ETOT;
}

__global__ void k_scatter(const int* __restrict__ ei) {
    int i = blockIdx.x * blockDim.x + threadIdx.x;
    if (i >= ETOT) return;
    int src, dst;
    if (i < NE) { src = __ldg(&ei[i]); dst = __ldg(&ei[NE + i]); }
    else        { src = i - NE; dst = src; }
    int p = atomicAdd(&g_pos[dst], 1);
    g_csr[p] = src;
}

// ---------------- tf32 tensor-core GEMM: g_h[M,256] = A[M,K] @ B[K,256] ----------------
__global__ void __launch_bounds__(256) k_gemm_tf32(const float* __restrict__ A,
                                                   const float* __restrict__ B,
                                                   int M, int K, int useFeat) {
    __shared__ unsigned As[2][16][136];
    __shared__ unsigned Bs[2][16][136];
    const float* Ap = useFeat ? g_feat : A;

    int tid = threadIdx.x;
    int lane = tid & 31;
    int wid = tid >> 5;
    int warp_m = wid >> 2;   // 0..1
    int warp_n = wid & 3;    // 0..3
    int gid = lane >> 2;     // 0..7
    int tig = lane & 3;      // 0..3

    int colBlk = blockIdx.x & 1;
    int rowBlk = blockIdx.x >> 1;
    int row0 = rowBlk * 128;
    int col0 = colBlk * 128;

    int NC = K / 16;
    float acc[4][4][4];
#pragma unroll
    for (int mt = 0; mt < 4; mt++)
#pragma unroll
        for (int nt = 0; nt < 4; nt++)
#pragma unroll
            for (int q = 0; q < 4; q++) acc[mt][nt][q] = 0.f;

    int aRow = tid >> 2;
    int aK4 = (tid & 3) * 4;
    int bK = tid >> 5;
    int bN = lane * 4;

    float4 aReg[2], bReg[2];

    {
        int k0 = 0;
#pragma unroll
        for (int it = 0; it < 2; it++) {
            int r = row0 + aRow + it * 64;
            aReg[it] = (r < M) ? *(const float4*)(Ap + (size_t)r * K + k0 + aK4)
                               : make_float4(0.f, 0.f, 0.f, 0.f);
            bReg[it] = *(const float4*)(B + (size_t)(k0 + bK + it * 8) * HCC + col0 + bN);
        }
#pragma unroll
        for (int it = 0; it < 2; it++) {
            int rr = aRow + it * 64;
            As[0][aK4 + 0][rr] = f2tf(aReg[it].x);
            As[0][aK4 + 1][rr] = f2tf(aReg[it].y);
            As[0][aK4 + 2][rr] = f2tf(aReg[it].z);
            As[0][aK4 + 3][rr] = f2tf(aReg[it].w);
            unsigned* bp = &Bs[0][bK + it * 8][bN];
            bp[0] = f2tf(bReg[it].x);
            bp[1] = f2tf(bReg[it].y);
            bp[2] = f2tf(bReg[it].z);
            bp[3] = f2tf(bReg[it].w);
        }
    }
    __syncthreads();

    for (int c = 0; c < NC; c++) {
        int buf = c & 1;
        if (c + 1 < NC) {
            int k0 = (c + 1) * 16;
#pragma unroll
            for (int it = 0; it < 2; it++) {
                int r = row0 + aRow + it * 64;
                aReg[it] = (r < M) ? *(const float4*)(Ap + (size_t)r * K + k0 + aK4)
                                   : make_float4(0.f, 0.f, 0.f, 0.f);
                bReg[it] = *(const float4*)(B + (size_t)(k0 + bK + it * 8) * HCC + col0 + bN);
            }
        }
        int mrow = warp_m * 64;
        int ncol = warp_n * 32;
#pragma unroll
        for (int ks = 0; ks < 2; ks++) {
            unsigned af[4][4], bf[4][2];
#pragma unroll
            for (int mt = 0; mt < 4; mt++) {
                int rb = mrow + mt * 16 + gid;
                af[mt][0] = As[buf][ks * 8 + tig][rb];
                af[mt][1] = As[buf][ks * 8 + tig][rb + 8];
                af[mt][2] = As[buf][ks * 8 + tig + 4][rb];
                af[mt][3] = As[buf][ks * 8 + tig + 4][rb + 8];
            }
#pragma unroll
            for (int nt = 0; nt < 4; nt++) {
                int nb = ncol + nt * 8 + gid;
                bf[nt][0] = Bs[buf][ks * 8 + tig][nb];
                bf[nt][1] = Bs[buf][ks * 8 + tig + 4][nb];
            }
#pragma unroll
            for (int mt = 0; mt < 4; mt++)
#pragma unroll
                for (int nt = 0; nt < 4; nt++)
                    mma_tf32(acc[mt][nt], af[mt], bf[nt]);
        }
        __syncthreads();
        if (c + 1 < NC) {
            int nb = (c + 1) & 1;
#pragma unroll
            for (int it = 0; it < 2; it++) {
                int rr = aRow + it * 64;
                As[nb][aK4 + 0][rr] = f2tf(aReg[it].x);
                As[nb][aK4 + 1][rr] = f2tf(aReg[it].y);
                As[nb][aK4 + 2][rr] = f2tf(aReg[it].z);
                As[nb][aK4 + 3][rr] = f2tf(aReg[it].w);
                unsigned* bp = &Bs[nb][bK + it * 8][bN];
                bp[0] = f2tf(bReg[it].x);
                bp[1] = f2tf(bReg[it].y);
                bp[2] = f2tf(bReg[it].z);
                bp[3] = f2tf(bReg[it].w);
            }
            __syncthreads();
        }
    }

#pragma unroll
    for (int mt = 0; mt < 4; mt++) {
        int r = row0 + warp_m * 64 + mt * 16 + gid;
#pragma unroll
        for (int nt = 0; nt < 4; nt++) {
            int cc = col0 + warp_n * 32 + nt * 8 + tig * 2;
            if (r < M)
                *(float2*)(g_h + (size_t)r * HCC + cc) = make_float2(acc[mt][nt][0], acc[mt][nt][1]);
            if (r + 8 < M)
                *(float2*)(g_h + (size_t)(r + 8) * HCC + cc) = make_float2(acc[mt][nt][2], acc[mt][nt][3]);
        }
    }
}

// ---------------- per-node attention scores: warp per node, float4 ----------------
__global__ void __launch_bounds__(256) k_scores(const float* __restrict__ a_src,
                                                const float* __restrict__ a_dst) {
    int w = (blockIdx.x * blockDim.x + threadIdx.x) >> 5;
    int lane = threadIdx.x & 31;
    if (w >= NN) return;
    const float4* hp = (const float4*)(g_h + (size_t)w * HCC + lane * 8);
    float4 h0 = __ldg(hp), h1 = __ldg(hp + 1);
    int head = lane >> 3;
    int cb = (lane & 7) * 8;
    const float4* as = (const float4*)(a_src + head * HD + cb);
    const float4* ad = (const float4*)(a_dst + head * HD + cb);
    float4 a0 = __ldg(as), a1 = __ldg(as + 1);
    float4 d0 = __ldg(ad), d1 = __ldg(ad + 1);
    float p1 = h0.x * a0.x + h0.y * a0.y + h0.z * a0.z + h0.w * a0.w
             + h1.x * a1.x + h1.y * a1.y + h1.z * a1.z + h1.w * a1.w;
    float p2 = h0.x * d0.x + h0.y * d0.y + h0.z * d0.z + h0.w * d0.w
             + h1.x * d1.x + h1.y * d1.y + h1.z * d1.z + h1.w * d1.w;
#pragma unroll
    for (int o = 1; o < 8; o <<= 1) {
        p1 += __shfl_xor_sync(0xffffffffu, p1, o);
        p2 += __shfl_xor_sync(0xffffffffu, p2, o);
    }
    if ((lane & 7) == 0) {
        g_ssrc[w * 4 + head] = p1;
        g_sdst[w * 4 + head] = p2;
    }
}

// ---------------- GAT aggregate: warp per dst, single-pass (no max-shift needed) ----------------
// Chunked: 32 edges at a time. One coalesced csr load + 32 parallel score loads + exps,
// weights staged in smem; inner loop is pure high-MLP gather+FMA.
__global__ void __launch_bounds__(256) k_aggregate(const float* __restrict__ bias) {
    __shared__ float4 s_w[8][32];
    int wid = threadIdx.x >> 5;
    int lane = threadIdx.x & 31;
    int w = blockIdx.x * 8 + wid;
    if (w >= NN) return;
    int beg = g_off[w], end = g_off[w + 1];
    int head = lane >> 3;

    float4 sd = __ldg((const float4*)(g_sdst + w * 4));

    float4 acc0 = make_float4(0.f, 0.f, 0.f, 0.f);
    float4 acc1 = make_float4(0.f, 0.f, 0.f, 0.f);
    float4 den = make_float4(0.f, 0.f, 0.f, 0.f);

    for (int base = beg; base < end; base += 32) {
        int n = end - base;
        if (n > 32) n = 32;
        int u = 0;
        float4 w4 = make_float4(0.f, 0.f, 0.f, 0.f);
        if (lane < n) {
            u = __ldg(&g_csr[base + lane]);
            float4 ss = __ldg((const float4*)(g_ssrc + 4 * u));
            float e0 = ss.x + sd.x; e0 = fmaxf(e0, NEG_SLOPE * e0);
            float e1 = ss.y + sd.y; e1 = fmaxf(e1, NEG_SLOPE * e1);
            float e2 = ss.z + sd.z; e2 = fmaxf(e2, NEG_SLOPE * e2);
            float e3 = ss.w + sd.w; e3 = fmaxf(e3, NEG_SLOPE * e3);
            w4 = make_float4(__expf(e0), __expf(e1), __expf(e2), __expf(e3));
            den.x += w4.x; den.y += w4.y; den.z += w4.z; den.w += w4.w;
        }
        s_w[wid][lane] = w4;
        __syncwarp();
#pragma unroll 4
        for (int j = 0; j < n; j++) {
            int uj = __shfl_sync(0xffffffffu, u, j);
            float wk = ((const float*)&s_w[wid][j])[head];  // broadcast within 8-lane head group
            const float4* hp = (const float4*)(g_h + (size_t)uj * HCC + lane * 8);
            float4 h0 = __ldg(hp), h1 = __ldg(hp + 1);
            acc0.x += wk * h0.x; acc0.y += wk * h0.y; acc0.z += wk * h0.z; acc0.w += wk * h0.w;
            acc1.x += wk * h1.x; acc1.y += wk * h1.y; acc1.z += wk * h1.z; acc1.w += wk * h1.w;
        }
        __syncwarp();
    }

    // per-head denominator: reduce each component over all lanes
    den.x = warpSum(den.x);
    den.y = warpSum(den.y);
    den.z = warpSum(den.z);
    den.w = warpSum(den.w);
    float dh = head == 0 ? den.x : head == 1 ? den.y : head == 2 ? den.z : den.w;
    float inv = 1.0f / (dh + 1e-16f);
    acc0.x *= inv; acc0.y *= inv; acc0.z *= inv; acc0.w *= inv;
    acc1.x *= inv; acc1.y *= inv; acc1.z *= inv; acc1.w *= inv;

    // sum over the 4 heads (lanes l, l^8, l^16, l^24 hold the same within-head channels)
#pragma unroll
    for (int o = 8; o < 32; o <<= 1) {
        acc0.x += __shfl_xor_sync(0xffffffffu, acc0.x, o);
        acc0.y += __shfl_xor_sync(0xffffffffu, acc0.y, o);
        acc0.z += __shfl_xor_sync(0xffffffffu, acc0.z, o);
        acc0.w += __shfl_xor_sync(0xffffffffu, acc0.w, o);
        acc1.x += __shfl_xor_sync(0xffffffffu, acc1.x, o);
        acc1.y += __shfl_xor_sync(0xffffffffu, acc1.y, o);
        acc1.z += __shfl_xor_sync(0xffffffffu, acc1.z, o);
        acc1.w += __shfl_xor_sync(0xffffffffu, acc1.w, o);
    }
    if (lane < 8) {
        const float4* bp = (const float4*)(bias + lane * 8);
        float4 b0 = __ldg(bp), b1 = __ldg(bp + 1);
        float4 o0 = make_float4(acc0.x * 0.25f + b0.x, acc0.y * 0.25f + b0.y,
                                acc0.z * 0.25f + b0.z, acc0.w * 0.25f + b0.w);
        float4 o1 = make_float4(acc1.x * 0.25f + b1.x, acc1.y * 0.25f + b1.y,
                                acc1.z * 0.25f + b1.z, acc1.w * 0.25f + b1.w);
        float4* op = (float4*)(g_feat + (size_t)w * HD + lane * 8);
        op[0] = o0;
        op[1] = o1;
    }
}

// ---------------- GraphNorm (single-pass stats via E[x^2]) ----------------
__global__ void k_zero_stats() {
    int t = threadIdx.x;
    if (t < HD) { g_cs1[t] = 0.f; g_cs2[t] = 0.f; }
}

__global__ void k_colreduce() {
    int t = threadIdx.x;
    int c = t & 63;
    int g = t >> 6;  // 4 row-groups
    float a1 = 0.f, a2 = 0.f;
    for (int r = blockIdx.x * 4 + g; r < NN; r += gridDim.x * 4) {
        float v = g_feat[(size_t)r * HD + c];
        a1 += v;
        a2 += v * v;
    }
    __shared__ float s1[256], s2[256];
    s1[t] = a1; s2[t] = a2;
    __syncthreads();
    if (t < 64) {
        float r1 = s1[t] + s1[t + 64] + s1[t + 128] + s1[t + 192];
        float r2 = s2[t] + s2[t + 64] + s2[t + 128] + s2[t + 192];
        atomicAdd(&g_cs1[c], r1);
        atomicAdd(&g_cs2[c], r2);
    }
}

__global__ void k_norm_relu(const float* __restrict__ w, const float* __restrict__ b,
                            const float* __restrict__ gs) {
    int idx = blockIdx.x * blockDim.x + threadIdx.x;   // float4 index
    if (idx >= NN * (HD / 4)) return;
    int c0 = (idx & 15) * 4;
    float4 v = *((const float4*)g_feat + idx);
    float o[4];
#pragma unroll
    for (int q = 0; q < 4; q++) {
        int c = c0 + q;
        float mu = g_cs1[c] * (1.f / NN);
        float m2 = g_cs2[c] * (1.f / NN);
        float tt = mu * __ldg(&gs[c]);
        float var = m2 - 2.f * tt * mu + tt * tt;
        float r = rsqrtf(var + 1e-5f);
        float xc = ((const float*)&v)[q] - tt;
        float t = __ldg(&w[c]) * xc * r + __ldg(&b[c]);
        o[q] = t > 0.f ? t : 0.f;
    }
    *((float4*)g_feat + idx) = make_float4(o[0], o[1], o[2], o[3]);
}

// ---------------- triplet gather + layernorm + fc ----------------
__global__ void __launch_bounds__(256) k_triplet(const int* __restrict__ trip,
        const float* __restrict__ lnw, const float* __restrict__ lnb,
        const float* __restrict__ fcw, const float* __restrict__ fcb,
        float* __restrict__ out) {
    int w = (blockIdx.x * blockDim.x + threadIdx.x) >> 5;
    int lane = threadIdx.x & 31;
    if (w >= NT) return;
    int n0 = __ldg(&trip[w * 4 + 0]);
    int n1 = __ldg(&trip[w * 4 + 1]);
    int n2 = __ldg(&trip[w * 4 + 2]);
    int n3 = __ldg(&trip[w * 4 + 3]);
    float v[8];
#pragma unroll
    for (int k = 0; k < 8; k++) {
        int i = lane + 32 * k;
        int node = (k < 2) ? n0 : (k < 4) ? n1 : (k < 6) ? n2 : n3;
        v[k] = __ldg(&g_feat[(size_t)node * HD + (i & 63)]);
    }
    float s = 0.f;
#pragma unroll
    for (int k = 0; k < 8; k++) s += v[k];
    s = warpSum(s);
    float mean = s * (1.f / 256.f);
    float q = 0.f;
#pragma unroll
    for (int k = 0; k < 8; k++) { float d = v[k] - mean; q += d * d; }
    q = warpSum(q);
    float r = rsqrtf(q * (1.f / 256.f) + 1e-5f);
    float acc = 0.f;
#pragma unroll
    for (int k = 0; k < 8; k++) {
        int i = lane + 32 * k;
        acc += ((v[k] - mean) * r * __ldg(&lnw[i]) + __ldg(&lnb[i])) * __ldg(&fcw[i]);
    }
    acc = warpSum(acc);
    if (lane == 0) out[w] = acc + fcb[0];
}

// ---------------- launch ----------------
extern "C" void kernel_launch(void* const* d_in, const int* in_sizes, int n_in,
                              void* d_out, int out_size) {
    const float* x   = (const float*)d_in[0];
    const float* W1  = (const float*)d_in[2];
    const float* as1 = (const float*)d_in[3];
    const float* ad1 = (const float*)d_in[4];
    const float* b1  = (const float*)d_in[5];
    const float* W2  = (const float*)d_in[6];
    const float* as2 = (const float*)d_in[7];
    const float* ad2 = (const float*)d_in[8];
    const float* b2  = (const float*)d_in[9];
    const float* g1w = (const float*)d_in[10];
    const float* g1b = (const float*)d_in[11];
    const float* g1s = (const float*)d_in[12];
    const float* g2w = (const float*)d_in[13];
    const float* g2b = (const float*)d_in[14];
    const float* g2s = (const float*)d_in[15];
    const float* lnw = (const float*)d_in[16];
    const float* lnb = (const float*)d_in[17];
    const float* fcw = (const float*)d_in[18];
    const float* fcb = (const float*)d_in[19];
    const int*   ei  = (const int*)d_in[20];
    const int*   trp = (const int*)d_in[21];
    float* out = (float*)d_out;

    // CSR build (dst-sorted adjacency incl. self loops)
    k_zero_deg<<<(NN + 255) / 256, 256>>>();
    k_hist<<<(ETOT + 255) / 256, 256>>>(ei);
    k_scan<<<1, 1024>>>();
    k_scatter<<<(ETOT + 255) / 256, 256>>>(ei);

    int gemmGrid = ((NN + 127) / 128) * 2;
    int warpGrid = (NN + 7) / 8;

    // ---- layer 1 ----
    k_gemm_tf32<<<gemmGrid, 256>>>(x, W1, NN, 128, 0);
    k_scores<<<warpGrid, 256>>>(as1, ad1);
    k_aggregate<<<warpGrid, 256>>>(b1);
    k_zero_stats<<<1, 128>>>();
    k_colreduce<<<128, 256>>>();
    k_norm_relu<<<(NN * 16 + 255) / 256, 256>>>(g1w, g1b, g1s);

    // ---- layer 2 ----
    k_gemm_tf32<<<gemmGrid, 256>>>(nullptr, W2, NN, 64, 1);
    k_scores<<<warpGrid, 256>>>(as2, ad2);
    k_aggregate<<<warpGrid, 256>>>(b2);
    k_zero_stats<<<1, 128>>>();
    k_colreduce<<<128, 256>>>();
    k_norm_relu<<<(NN * 16 + 255) / 256, 256>>>(g2w, g2b, g2s);

    // ---- triplet head ----
    k_triplet<<<(NT + 7) / 8, 256>>>(trp, lnw, lnb, fcw, fcb, out);
}

// round 5
// speedup vs baseline: 2.1935x; 1.2474x over previous
#include <cuda_runtime.h>
#include <cuda_fp16.h>

#define NN 50000
#define NE 800000
#define ETOT (NE + NN)
#define HD 64
#define HCC 256
#define NT 200000
#define NEG_SLOPE 0.2f

// ---------------- scratch (static device globals; no allocations) ----------------
__device__ __half2 g_hh[(size_t)NN * 128];   // transformed features fp16 [N, 256] as half2
__device__ float g_feat[(size_t)NN * HD];    // per-layer node output (pre-norm) [N, 64]
__device__ float g_ssrcA[NN * 4], g_sdstA[NN * 4];
__device__ float g_ssrcB[NN * 4], g_sdstB[NN * 4];
__device__ int   g_deg[NN];
__device__ int   g_off[NN + 1];
__device__ int   g_pos[NN];
__device__ int   g_csr[ETOT];
__device__ float g_cs1a[HD], g_cs2a[HD], g_cs1b[HD], g_cs2b[HD];

// ---------------- helpers ----------------
__device__ __forceinline__ float warpSum(float v) {
#pragma unroll
    for (int o = 16; o; o >>= 1) v += __shfl_xor_sync(0xffffffffu, v, o);
    return v;
}
__device__ __forceinline__ unsigned f2tf(float f) {
    unsigned r;
    asm("cvt.rna.tf32.f32 %0, %1;" : "=r"(r) : "f"(f));
    return r;
}
__device__ __forceinline__ void mma_tf32(float* d, const unsigned* a, const unsigned* b) {
    asm volatile(
        "mma.sync.aligned.m16n8k8.row.col.f32.tf32.tf32.f32 "
        "{%0,%1,%2,%3}, {%4,%5,%6,%7}, {%8,%9}, {%0,%1,%2,%3};"
        : "+f"(d[0]), "+f"(d[1]), "+f"(d[2]), "+f"(d[3])
        : "r"(a[0]), "r"(a[1]), "r"(a[2]), "r"(a[3]), "r"(b[0]), "r"(b[1]));
}

// ---------------- zero all accumulators ----------------
__global__ void k_zero() {
    int i = blockIdx.x * blockDim.x + threadIdx.x;
    if (i < NN) g_deg[i] = 0;
    if (i < NN * 4) {
        g_ssrcA[i] = 0.f; g_sdstA[i] = 0.f;
        g_ssrcB[i] = 0.f; g_sdstB[i] = 0.f;
    }
    if (i < HD) {
        g_cs1a[i] = 0.f; g_cs2a[i] = 0.f;
        g_cs1b[i] = 0.f; g_cs2b[i] = 0.f;
    }
}

// ---------------- CSR build ----------------
__global__ void k_hist(const int* __restrict__ ei) {
    int i = blockIdx.x * blockDim.x + threadIdx.x;
    if (i >= ETOT) return;
    int dst = (i < NE) ? __ldg(&ei[NE + i]) : (i - NE);
    atomicAdd(&g_deg[dst], 1);
}

__global__ void k_scan() {
    __shared__ int sm[1024];
    int t = threadIdx.x;
    const int per = (NN + 1023) / 1024;
    int base = t * per;
    int s = 0;
    for (int j = 0; j < per; j++) {
        int idx = base + j;
        if (idx < NN) s += g_deg[idx];
    }
    sm[t] = s;
    __syncthreads();
    for (int off = 1; off < 1024; off <<= 1) {
        int v = (t >= off) ? sm[t - off] : 0;
        __syncthreads();
        sm[t] += v;
        __syncthreads();
    }
    int run = sm[t] - s;  // exclusive prefix
    for (int j = 0; j < per; j++) {
        int idx = base + j;
        if (idx < NN) {
            g_off[idx] = run;
            g_pos[idx] = run;
            run += g_deg[idx];
        }
    }
    if (t == 0) g_off[NN] = ETOT;
}

__global__ void k_scatter(const int* __restrict__ ei) {
    int i = blockIdx.x * blockDim.x + threadIdx.x;
    if (i >= ETOT) return;
    int src, dst;
    if (i < NE) { src = __ldg(&ei[i]); dst = __ldg(&ei[NE + i]); }
    else        { src = i - NE; dst = src; }
    int p = atomicAdd(&g_pos[dst], 1);
    g_csr[p] = src;
}

// ---------------- tf32 GEMM + fused norm-on-load + fp16 store + fused scores ----------------
// layer==0: A = param (x), no input norm, scores -> A arrays
// layer==1: A = g_feat with graphnorm(stats a)+relu applied on load, scores -> B arrays
__global__ void __launch_bounds__(256) k_gemm(const float* __restrict__ A,
                                              const float* __restrict__ B,
                                              int M, int K, int layer,
                                              const float* __restrict__ av_src,
                                              const float* __restrict__ av_dst,
                                              const float* __restrict__ nw,
                                              const float* __restrict__ nb,
                                              const float* __restrict__ ns) {
    __shared__ unsigned As[2][16][136];
    __shared__ unsigned Bs[2][16][136];
    __shared__ float nsc[64], nsh[64];

    int tid = threadIdx.x;
    if (layer && tid < 64) {
        float mu = g_cs1a[tid] * (1.f / NN);
        float m2 = g_cs2a[tid] * (1.f / NN);
        float tt = mu * __ldg(&ns[tid]);
        float var = m2 - 2.f * tt * mu + tt * tt;
        float rs = rsqrtf(var + 1e-5f);
        float sc = __ldg(&nw[tid]) * rs;
        nsc[tid] = sc;
        nsh[tid] = __ldg(&nb[tid]) - tt * sc;
    }
    __syncthreads();

    const float* Ap = layer ? g_feat : A;

    int lane = tid & 31;
    int wid = tid >> 5;
    int warp_m = wid >> 2;   // 0..1
    int warp_n = wid & 3;    // 0..3
    int gid = lane >> 2;     // 0..7
    int tig = lane & 3;      // 0..3

    int colBlk = blockIdx.x & 1;
    int rowBlk = blockIdx.x >> 1;
    int row0 = rowBlk * 128;
    int col0 = colBlk * 128;

    int NC = K / 16;
    float acc[4][4][4];
#pragma unroll
    for (int mt = 0; mt < 4; mt++)
#pragma unroll
        for (int nt = 0; nt < 4; nt++)
#pragma unroll
            for (int q = 0; q < 4; q++) acc[mt][nt][q] = 0.f;

    int aRow = tid >> 2;
    int aK4 = (tid & 3) * 4;
    int bK = tid >> 5;
    int bN = lane * 4;

    float4 aReg[2], bReg[2];

    // A-load lambda behavior inline: load + optional norm+relu
    auto loadA = [&](int r, int k) -> float4 {
        if (r >= M) return make_float4(0.f, 0.f, 0.f, 0.f);
        float4 v = __ldg((const float4*)(Ap + (size_t)r * K + k));
        if (layer) {
            v.x = fmaxf(0.f, v.x * nsc[k + 0] + nsh[k + 0]);
            v.y = fmaxf(0.f, v.y * nsc[k + 1] + nsh[k + 1]);
            v.z = fmaxf(0.f, v.z * nsc[k + 2] + nsh[k + 2]);
            v.w = fmaxf(0.f, v.w * nsc[k + 3] + nsh[k + 3]);
        }
        return v;
    };

    {
#pragma unroll
        for (int it = 0; it < 2; it++) {
            aReg[it] = loadA(row0 + aRow + it * 64, aK4);
            bReg[it] = __ldg((const float4*)(B + (size_t)(bK + it * 8) * HCC + col0 + bN));
        }
#pragma unroll
        for (int it = 0; it < 2; it++) {
            int rr = aRow + it * 64;
            As[0][aK4 + 0][rr] = f2tf(aReg[it].x);
            As[0][aK4 + 1][rr] = f2tf(aReg[it].y);
            As[0][aK4 + 2][rr] = f2tf(aReg[it].z);
            As[0][aK4 + 3][rr] = f2tf(aReg[it].w);
            unsigned* bp = &Bs[0][bK + it * 8][bN];
            bp[0] = f2tf(bReg[it].x);
            bp[1] = f2tf(bReg[it].y);
            bp[2] = f2tf(bReg[it].z);
            bp[3] = f2tf(bReg[it].w);
        }
    }
    __syncthreads();

    for (int c = 0; c < NC; c++) {
        int buf = c & 1;
        if (c + 1 < NC) {
            int k0 = (c + 1) * 16;
#pragma unroll
            for (int it = 0; it < 2; it++) {
                aReg[it] = loadA(row0 + aRow + it * 64, k0 + aK4);
                bReg[it] = __ldg((const float4*)(B + (size_t)(k0 + bK + it * 8) * HCC + col0 + bN));
            }
        }
        int mrow = warp_m * 64;
        int ncol = warp_n * 32;
#pragma unroll
        for (int ks = 0; ks < 2; ks++) {
            unsigned af[4][4], bf[4][2];
#pragma unroll
            for (int mt = 0; mt < 4; mt++) {
                int rb = mrow + mt * 16 + gid;
                af[mt][0] = As[buf][ks * 8 + tig][rb];
                af[mt][1] = As[buf][ks * 8 + tig][rb + 8];
                af[mt][2] = As[buf][ks * 8 + tig + 4][rb];
                af[mt][3] = As[buf][ks * 8 + tig + 4][rb + 8];
            }
#pragma unroll
            for (int nt = 0; nt < 4; nt++) {
                int nb2 = ncol + nt * 8 + gid;
                bf[nt][0] = Bs[buf][ks * 8 + tig][nb2];
                bf[nt][1] = Bs[buf][ks * 8 + tig + 4][nb2];
            }
#pragma unroll
            for (int mt = 0; mt < 4; mt++)
#pragma unroll
                for (int nt = 0; nt < 4; nt++)
                    mma_tf32(acc[mt][nt], af[mt], bf[nt]);
        }
        __syncthreads();
        if (c + 1 < NC) {
            int nb = (c + 1) & 1;
#pragma unroll
            for (int it = 0; it < 2; it++) {
                int rr = aRow + it * 64;
                As[nb][aK4 + 0][rr] = f2tf(aReg[it].x);
                As[nb][aK4 + 1][rr] = f2tf(aReg[it].y);
                As[nb][aK4 + 2][rr] = f2tf(aReg[it].z);
                As[nb][aK4 + 3][rr] = f2tf(aReg[it].w);
                unsigned* bp = &Bs[nb][bK + it * 8][bN];
                bp[0] = f2tf(bReg[it].x);
                bp[1] = f2tf(bReg[it].y);
                bp[2] = f2tf(bReg[it].z);
                bp[3] = f2tf(bReg[it].w);
            }
            __syncthreads();
        }
    }

    // ---- epilogue 1: fp16 store of h ----
#pragma unroll
    for (int mt = 0; mt < 4; mt++) {
        int r = row0 + warp_m * 64 + mt * 16 + gid;
#pragma unroll
        for (int nt = 0; nt < 4; nt++) {
            int cc = col0 + warp_n * 32 + nt * 8 + tig * 2;
            if (r < M)
                g_hh[(size_t)r * 128 + cc / 2] = __floats2half2_rn(acc[mt][nt][0], acc[mt][nt][1]);
            if (r + 8 < M)
                g_hh[(size_t)(r + 8) * 128 + cc / 2] = __floats2half2_rn(acc[mt][nt][2], acc[mt][nt][3]);
        }
    }

    // ---- epilogue 2: fused attention scores (fp32 accuracy) ----
    // This warp's 32-col span lies in exactly one head.
    int head = (col0 + warp_n * 32) >> 6;
    float aS[8], aD[8];
#pragma unroll
    for (int nt = 0; nt < 4; nt++) {
        int ch = (col0 + warp_n * 32 + nt * 8 + tig * 2) & 63;
        aS[nt * 2 + 0] = __ldg(&av_src[head * 64 + ch]);
        aS[nt * 2 + 1] = __ldg(&av_src[head * 64 + ch + 1]);
        aD[nt * 2 + 0] = __ldg(&av_dst[head * 64 + ch]);
        aD[nt * 2 + 1] = __ldg(&av_dst[head * 64 + ch + 1]);
    }
    float* ssrc = layer ? g_ssrcB : g_ssrcA;
    float* sdst = layer ? g_sdstB : g_sdstA;
#pragma unroll
    for (int mt = 0; mt < 4; mt++) {
#pragma unroll
        for (int half = 0; half < 2; half++) {
            float ps = 0.f, pd = 0.f;
#pragma unroll
            for (int nt = 0; nt < 4; nt++) {
                float v0 = acc[mt][nt][half * 2 + 0];
                float v1 = acc[mt][nt][half * 2 + 1];
                ps += v0 * aS[nt * 2] + v1 * aS[nt * 2 + 1];
                pd += v0 * aD[nt * 2] + v1 * aD[nt * 2 + 1];
            }
            ps += __shfl_xor_sync(0xffffffffu, ps, 1);
            ps += __shfl_xor_sync(0xffffffffu, ps, 2);
            pd += __shfl_xor_sync(0xffffffffu, pd, 1);
            pd += __shfl_xor_sync(0xffffffffu, pd, 2);
            int r = row0 + warp_m * 64 + mt * 16 + gid + half * 8;
            if (tig == 0 && r < M) {
                atomicAdd(&ssrc[r * 4 + head], ps);
                atomicAdd(&sdst[r * 4 + head], pd);
            }
        }
    }
}

// ---------------- GAT aggregate (fp16 gather) + fused GraphNorm stats ----------------
// Grid: exactly NN/8 blocks of 256 (NN divisible by 8).
__global__ void __launch_bounds__(256) k_aggregate(const float* __restrict__ bias, int layer) {
    __shared__ float4 s_w[8][32];
    __shared__ float s_sum[64], s_sq[64];
    int tid = threadIdx.x;
    if (tid < 64) { s_sum[tid] = 0.f; s_sq[tid] = 0.f; }
    __syncthreads();

    int wid = tid >> 5;
    int lane = tid & 31;
    int w = blockIdx.x * 8 + wid;
    int beg = g_off[w], end = g_off[w + 1];
    int head = lane >> 3;

    const float* ssrc = layer ? g_ssrcB : g_ssrcA;
    const float* sdstp = layer ? g_sdstB : g_sdstA;
    float4 sd = __ldg((const float4*)(sdstp + w * 4));

    float4 acc0 = make_float4(0.f, 0.f, 0.f, 0.f);
    float4 acc1 = make_float4(0.f, 0.f, 0.f, 0.f);
    float4 den = make_float4(0.f, 0.f, 0.f, 0.f);

    for (int base = beg; base < end; base += 32) {
        int n = end - base;
        if (n > 32) n = 32;
        int u = 0;
        float4 w4 = make_float4(0.f, 0.f, 0.f, 0.f);
        if (lane < n) {
            u = __ldg(&g_csr[base + lane]);
            float4 ss = __ldg((const float4*)(ssrc + 4 * u));
            float e0 = ss.x + sd.x; e0 = fmaxf(e0, NEG_SLOPE * e0);
            float e1 = ss.y + sd.y; e1 = fmaxf(e1, NEG_SLOPE * e1);
            float e2 = ss.z + sd.z; e2 = fmaxf(e2, NEG_SLOPE * e2);
            float e3 = ss.w + sd.w; e3 = fmaxf(e3, NEG_SLOPE * e3);
            w4 = make_float4(__expf(e0), __expf(e1), __expf(e2), __expf(e3));
            den.x += w4.x; den.y += w4.y; den.z += w4.z; den.w += w4.w;
        }
        s_w[wid][lane] = w4;
        __syncwarp();
#pragma unroll 4
        for (int j = 0; j < n; j++) {
            int uj = __shfl_sync(0xffffffffu, u, j);
            float wk = ((const float*)&s_w[wid][j])[head];
            uint4 pk = __ldg((const uint4*)(g_hh + (size_t)uj * 128 + lane * 4));
            float2 f0 = __half22float2(*(__half2*)&pk.x);
            float2 f1 = __half22float2(*(__half2*)&pk.y);
            float2 f2 = __half22float2(*(__half2*)&pk.z);
            float2 f3 = __half22float2(*(__half2*)&pk.w);
            acc0.x += wk * f0.x; acc0.y += wk * f0.y; acc0.z += wk * f1.x; acc0.w += wk * f1.y;
            acc1.x += wk * f2.x; acc1.y += wk * f2.y; acc1.z += wk * f3.x; acc1.w += wk * f3.y;
        }
        __syncwarp();
    }

    den.x = warpSum(den.x);
    den.y = warpSum(den.y);
    den.z = warpSum(den.z);
    den.w = warpSum(den.w);
    float dh = head == 0 ? den.x : head == 1 ? den.y : head == 2 ? den.z : den.w;
    float inv = 1.0f / (dh + 1e-16f);
    acc0.x *= inv; acc0.y *= inv; acc0.z *= inv; acc0.w *= inv;
    acc1.x *= inv; acc1.y *= inv; acc1.z *= inv; acc1.w *= inv;

#pragma unroll
    for (int o = 8; o < 32; o <<= 1) {
        acc0.x += __shfl_xor_sync(0xffffffffu, acc0.x, o);
        acc0.y += __shfl_xor_sync(0xffffffffu, acc0.y, o);
        acc0.z += __shfl_xor_sync(0xffffffffu, acc0.z, o);
        acc0.w += __shfl_xor_sync(0xffffffffu, acc0.w, o);
        acc1.x += __shfl_xor_sync(0xffffffffu, acc1.x, o);
        acc1.y += __shfl_xor_sync(0xffffffffu, acc1.y, o);
        acc1.z += __shfl_xor_sync(0xffffffffu, acc1.z, o);
        acc1.w += __shfl_xor_sync(0xffffffffu, acc1.w, o);
    }
    if (lane < 8) {
        const float4* bp = (const float4*)(bias + lane * 8);
        float4 b0 = __ldg(bp), b1 = __ldg(bp + 1);
        float ov[8];
        ov[0] = acc0.x * 0.25f + b0.x; ov[1] = acc0.y * 0.25f + b0.y;
        ov[2] = acc0.z * 0.25f + b0.z; ov[3] = acc0.w * 0.25f + b0.w;
        ov[4] = acc1.x * 0.25f + b1.x; ov[5] = acc1.y * 0.25f + b1.y;
        ov[6] = acc1.z * 0.25f + b1.z; ov[7] = acc1.w * 0.25f + b1.w;
        float4* op = (float4*)(g_feat + (size_t)w * HD + lane * 8);
        op[0] = make_float4(ov[0], ov[1], ov[2], ov[3]);
        op[1] = make_float4(ov[4], ov[5], ov[6], ov[7]);
        int cb = lane * 8;
#pragma unroll
        for (int q = 0; q < 8; q++) {
            atomicAdd(&s_sum[cb + q], ov[q]);
            atomicAdd(&s_sq[cb + q], ov[q] * ov[q]);
        }
    }
    __syncthreads();
    if (tid < 64) {
        atomicAdd(layer ? &g_cs1b[tid] : &g_cs1a[tid], s_sum[tid]);
        atomicAdd(layer ? &g_cs2b[tid] : &g_cs2a[tid], s_sq[tid]);
    }
}

// ---------------- triplet: fused graphnorm(layer2)+relu + layernorm + fc ----------------
__global__ void __launch_bounds__(256) k_triplet(const int* __restrict__ trip,
        const float* __restrict__ g2w, const float* __restrict__ g2b, const float* __restrict__ g2s,
        const float* __restrict__ lnw, const float* __restrict__ lnb,
        const float* __restrict__ fcw, const float* __restrict__ fcb,
        float* __restrict__ out) {
    __shared__ float nsc[64], nsh[64];
    int tid = threadIdx.x;
    if (tid < 64) {
        float mu = g_cs1b[tid] * (1.f / NN);
        float m2 = g_cs2b[tid] * (1.f / NN);
        float tt = mu * __ldg(&g2s[tid]);
        float var = m2 - 2.f * tt * mu + tt * tt;
        float rs = rsqrtf(var + 1e-5f);
        float sc = __ldg(&g2w[tid]) * rs;
        nsc[tid] = sc;
        nsh[tid] = __ldg(&g2b[tid]) - tt * sc;
    }
    __syncthreads();

    int w = blockIdx.x * 8 + (tid >> 5);
    int lane = tid & 31;
    int n0 = __ldg(&trip[w * 4 + 0]);
    int n1 = __ldg(&trip[w * 4 + 1]);
    int n2 = __ldg(&trip[w * 4 + 2]);
    int n3 = __ldg(&trip[w * 4 + 3]);
    float v[8];
#pragma unroll
    for (int k = 0; k < 8; k++) {
        int i = lane + 32 * k;
        int node = (k < 2) ? n0 : (k < 4) ? n1 : (k < 6) ? n2 : n3;
        int ch = i & 63;
        float raw = __ldg(&g_feat[(size_t)node * HD + ch]);
        v[k] = fmaxf(0.f, raw * nsc[ch] + nsh[ch]);
    }
    float s = 0.f;
#pragma unroll
    for (int k = 0; k < 8; k++) s += v[k];
    s = warpSum(s);
    float mean = s * (1.f / 256.f);
    float q = 0.f;
#pragma unroll
    for (int k = 0; k < 8; k++) { float d = v[k] - mean; q += d * d; }
    q = warpSum(q);
    float r = rsqrtf(q * (1.f / 256.f) + 1e-5f);
    float acc = 0.f;
#pragma unroll
    for (int k = 0; k < 8; k++) {
        int i = lane + 32 * k;
        acc += ((v[k] - mean) * r * __ldg(&lnw[i]) + __ldg(&lnb[i])) * __ldg(&fcw[i]);
    }
    acc = warpSum(acc);
    if (lane == 0) out[w] = acc + fcb[0];
}

// ---------------- launch ----------------
extern "C" void kernel_launch(void* const* d_in, const int* in_sizes, int n_in,
                              void* d_out, int out_size) {
    const float* x   = (const float*)d_in[0];
    const float* W1  = (const float*)d_in[2];
    const float* as1 = (const float*)d_in[3];
    const float* ad1 = (const float*)d_in[4];
    const float* b1  = (const float*)d_in[5];
    const float* W2  = (const float*)d_in[6];
    const float* as2 = (const float*)d_in[7];
    const float* ad2 = (const float*)d_in[8];
    const float* b2  = (const float*)d_in[9];
    const float* g1w = (const float*)d_in[10];
    const float* g1b = (const float*)d_in[11];
    const float* g1s = (const float*)d_in[12];
    const float* g2w = (const float*)d_in[13];
    const float* g2b = (const float*)d_in[14];
    const float* g2s = (const float*)d_in[15];
    const float* lnw = (const float*)d_in[16];
    const float* lnb = (const float*)d_in[17];
    const float* fcw = (const float*)d_in[18];
    const float* fcb = (const float*)d_in[19];
    const int*   ei  = (const int*)d_in[20];
    const int*   trp = (const int*)d_in[21];
    float* out = (float*)d_out;

    int gemmGrid = ((NN + 127) / 128) * 2;

    k_zero<<<(NN * 4 + 255) / 256, 256>>>();
    k_hist<<<(ETOT + 255) / 256, 256>>>(ei);
    k_scan<<<1, 1024>>>();
    k_scatter<<<(ETOT + 255) / 256, 256>>>(ei);

    // layer 1: gemm (+fp16 h, +scores), aggregate (+stats)
    k_gemm<<<gemmGrid, 256>>>(x, W1, NN, 128, 0, as1, ad1, nullptr, nullptr, nullptr);
    k_aggregate<<<NN / 8, 256>>>(b1, 0);

    // layer 2: gemm with fused norm+relu on load
    k_gemm<<<gemmGrid, 256>>>(nullptr, W2, NN, 64, 1, as2, ad2, g1w, g1b, g1s);
    k_aggregate<<<NN / 8, 256>>>(b2, 1);

    // head: fused norm+relu + layernorm + fc
    k_triplet<<<NT / 8, 256>>>(trp, g2w, g2b, g2s, lnw, lnb, fcw, fcb, out);
}